// round 1
// baseline (speedup 1.0000x reference)
#include <cuda_runtime.h>
#include <math.h>

#define BATCH   128
#define IN_DIM  784
#define HIDDEN  100
#define MODES   10
#define NSTATES 2002
#define NCLS    10

// ---------------- scratch (__device__ globals; no allocation allowed) ------
__device__ float2  g_A[BATCH * 50];          // A[b, p, j] complex, p<10, j<5
__device__ float   g_prob[BATCH * NSTATES];  // |amp|^2
__device__ unsigned g_states[NSTATES];       // 5 nibbles: row indices m0..m4
__device__ float   g_invfact[NSTATES];       // 1 / prod(factorial(multiplicity))

__device__ __forceinline__ float2 cmul(float2 a, float2 b) {
    return make_float2(fmaf(a.x, b.x, -(a.y * b.y)),
                       fmaf(a.x, b.y,  a.y * b.x));
}

// ---------------- kernel 0: unrank combinations_with_replacement ----------
// state s -> sorted tuple (m0<=..<=m4), mi in [0,9].  Map to strict
// combination n_i = m_i + i of C(14,5), lex order preserved.
__global__ void k_init() {
    int s = blockIdx.x * blockDim.x + threadIdx.x;
    if (s >= NSTATES) return;
    int r = s, prev = 0;
    int m[5];
#pragma unroll
    for (int i = 0; i < 5; i++) {
        int v = prev;
        for (;;) {
            if (v > 13) { m[i] = 13 - i; break; }   // safety (never hit for valid rank)
            int n = 13 - v, k = 4 - i;
            unsigned c = 1;
            for (int t = 0; t < k; t++) c = c * (unsigned)(n - t) / (unsigned)(t + 1);
            if (n < k) c = 0;
            if ((unsigned)r < c) { m[i] = v - i; prev = v + 1; break; }
            r -= (int)c;
            v++;
        }
    }
    unsigned u = 0;
    int fact = 1, run = 1;
#pragma unroll
    for (int i = 0; i < 5; i++) {
        u |= ((unsigned)m[i]) << (4 * i);
        if (i && m[i] == m[i - 1]) { run++; fact *= run; }
        else run = 1;
    }
    g_states[s]  = u;
    g_invfact[s] = 1.0f / (float)fact;
}

// ---------------- kernel 1: MLP + phase + A -------------------------------
__global__ void k_mlp(const float* __restrict__ x,  const float* __restrict__ W1,
                      const float* __restrict__ b1,
                      const float* __restrict__ wlre, const float* __restrict__ wlim,
                      const float* __restrict__ wrre, const float* __restrict__ wrim) {
    int b   = blockIdx.x;
    int tid = threadIdx.x;
    __shared__ __align__(16) float xs[IN_DIM];
    __shared__ float  hs[HIDDEN];
    __shared__ float2 ph[MODES];

    for (int i = tid; i < IN_DIM; i += blockDim.x) xs[i] = x[b * IN_DIM + i];
    __syncthreads();

    if (tid < HIDDEN) {
        const float4* x4 = (const float4*)xs;
        const float4* w4 = (const float4*)(W1 + tid * IN_DIM);
        float a0 = 0.f, a1 = 0.f, a2 = 0.f, a3 = 0.f;
#pragma unroll 4
        for (int i = 0; i < IN_DIM / 4; i++) {
            float4 xv = x4[i], wv = w4[i];
            a0 = fmaf(xv.x, wv.x, a0); a1 = fmaf(xv.y, wv.y, a1);
            a2 = fmaf(xv.z, wv.z, a2); a3 = fmaf(xv.w, wv.w, a3);
        }
        float z = (a0 + a1) + (a2 + a3) + b1[tid];
        hs[tid] = 1.0f / (1.0f + expf(-z));
    }
    __syncthreads();

    if (tid < MODES) {
        float th = 0.f;
#pragma unroll
        for (int j = 0; j < 10; j++) th += hs[j * 10 + tid];
        float sn, cn;
        sincosf(th, &sn, &cn);
        ph[tid] = make_float2(cn, sn);
    }
    __syncthreads();

    if (tid < 50) {
        int p = tid / 5, j = tid % 5, c = 2 * j;  // IN_COLS = {0,2,4,6,8}
        float2 acc = make_float2(0.f, 0.f);
#pragma unroll
        for (int q = 0; q < MODES; q++) {
            float2 wr = make_float2(wrre[p * 10 + q], wrim[p * 10 + q]);
            float2 wl = make_float2(wlre[q * 10 + c], wlim[q * 10 + c]);
            float2 t  = cmul(wr, ph[q]);
            t = cmul(t, wl);
            acc.x += t.x; acc.y += t.y;
        }
        g_A[b * 50 + tid] = acc;
    }
}

// ---------------- kernel 2: 5x5 complex permanents (Ryser + Gray code) ----
__global__ void __launch_bounds__(256) k_perm() {
    int b = blockIdx.y;
    int s = blockIdx.x * 256 + threadIdx.x;
    __shared__ float2 Ash[50];
    if (threadIdx.x < 50) Ash[threadIdx.x] = g_A[b * 50 + threadIdx.x];
    __syncthreads();
    if (s >= NSTATES) return;

    unsigned u = g_states[s];
    float2 row[5][5];
#pragma unroll
    for (int n = 0; n < 5; n++) {
        int r = (u >> (4 * n)) & 15;
#pragma unroll
        for (int j = 0; j < 5; j++) row[n][j] = Ash[r * 5 + j];
    }

    float2 cs[5];
#pragma unroll
    for (int j = 0; j < 5; j++) cs[j] = make_float2(0.f, 0.f);
    float2 acc = make_float2(0.f, 0.f);

    unsigned g = 0;
#pragma unroll
    for (int k = 1; k < 32; k++) {
        // gray code: toggled bit = ctz(k); all of this folds at compile time
        unsigned ng = (unsigned)k ^ ((unsigned)k >> 1);
        int rb = (k & 1) ? 0 : (k & 2) ? 1 : (k & 4) ? 2 : (k & 8) ? 3 : 4;
        float sg = ((ng >> rb) & 1u) ? 1.f : -1.f;
#pragma unroll
        for (int j = 0; j < 5; j++) {
            cs[j].x = fmaf(sg, row[rb][j].x, cs[j].x);
            cs[j].y = fmaf(sg, row[rb][j].y, cs[j].y);
        }
        float2 pr = cs[0];
#pragma unroll
        for (int j = 1; j < 5; j++) pr = cmul(pr, cs[j]);
        float s2 = (k & 1) ? 1.f : -1.f;   // sign = (-1)^(5 - popcount(subset))
        acc.x = fmaf(s2, pr.x, acc.x);
        acc.y = fmaf(s2, pr.y, acc.y);
        g = ng;
    }
    (void)g;
    g_prob[b * NSTATES + s] = (acc.x * acc.x + acc.y * acc.y) * g_invfact[s];
}

// ---------------- kernel 3: prob @ W2^T + b2 ------------------------------
__global__ void k_out(const float* __restrict__ W2, const float* __restrict__ b2,
                      float* __restrict__ out) {
    int b = blockIdx.x;
    int tid = threadIdx.x;   // 256 threads
    float acc[NCLS];
#pragma unroll
    for (int c = 0; c < NCLS; c++) acc[c] = 0.f;

    for (int s = tid; s < NSTATES; s += 256) {
        float p = g_prob[b * NSTATES + s];
#pragma unroll
        for (int c = 0; c < NCLS; c++)
            acc[c] = fmaf(p, W2[c * NSTATES + s], acc[c]);
    }

    __shared__ float red[NCLS][8];
    int lane = tid & 31, w = tid >> 5;
#pragma unroll
    for (int c = 0; c < NCLS; c++) {
        float v = acc[c];
#pragma unroll
        for (int o = 16; o; o >>= 1) v += __shfl_down_sync(0xffffffffu, v, o);
        if (lane == 0) red[c][w] = v;
    }
    __syncthreads();
    if (tid < NCLS) {
        float v = 0.f;
#pragma unroll
        for (int ww = 0; ww < 8; ww++) v += red[tid][ww];
        out[b * NCLS + tid] = v + b2[tid];
    }
}

// ---------------- launch ---------------------------------------------------
extern "C" void kernel_launch(void* const* d_in, const int* in_sizes, int n_in,
                              void* d_out, int out_size) {
    const float* x    = (const float*)d_in[0];
    const float* W1   = (const float*)d_in[1];
    const float* b1   = (const float*)d_in[2];
    const float* wlre = (const float*)d_in[3];
    const float* wlim = (const float*)d_in[4];
    const float* wrre = (const float*)d_in[5];
    const float* wrim = (const float*)d_in[6];
    const float* W2   = (const float*)d_in[7];
    const float* b2   = (const float*)d_in[8];
    float* out = (float*)d_out;

    k_init<<<2, 1024>>>();
    k_mlp<<<BATCH, 128>>>(x, W1, b1, wlre, wlim, wrre, wrim);
    dim3 gp((NSTATES + 255) / 256, BATCH);
    k_perm<<<gp, 256>>>();
    k_out<<<BATCH, 256>>>(W2, b2, out);
}

// round 3
// speedup vs baseline: 1.0057x; 1.0057x over previous
#include <cuda_runtime.h>
#include <math.h>

#define BATCH   128
#define IN_DIM  784
#define HIDDEN  100
#define MODES   10
#define NSTATES 2002
#define NCLS    10
#define SCHUNKS 8

// ---------------- scratch (__device__ globals; no allocation allowed) ------
__device__ float2   g_A[BATCH * 50];                    // A[b, p, j] complex
__device__ unsigned g_states[NSTATES];                  // 5 nibbles: row indices
__device__ float    g_invfact[NSTATES];                 // 1/prod(fact) premultiplied
__device__ float    g_part[BATCH * SCHUNKS * NCLS];     // partial W2 sums

__device__ __forceinline__ float2 cmul(float2 a, float2 b) {
    return make_float2(fmaf(a.x, b.x, -(a.y * b.y)),
                       fmaf(a.x, b.y,  a.y * b.x));
}

// ---------------- kernel 1: init (blocks 0..15) + MLP/phase/A (blocks 16..79)
__global__ void k_front(const float* __restrict__ x,  const float* __restrict__ W1,
                        const float* __restrict__ b1,
                        const float* __restrict__ wlre, const float* __restrict__ wlim,
                        const float* __restrict__ wrre, const float* __restrict__ wrim) {
    int blk = blockIdx.x, tid = threadIdx.x;

    if (blk < 16) {
        // ---- unrank combinations_with_replacement(10, 5), rank s ----
        int s = blk * 128 + tid;
        if (s >= NSTATES) return;
        int r = s, prev = 0;
        int m[5];
#pragma unroll
        for (int i = 0; i < 5; i++) {
            int v = prev;
            for (;;) {
                if (v > 13) { m[i] = 13 - i; break; }
                int n = 13 - v, k = 4 - i;
                unsigned c = 1;
                for (int t = 0; t < k; t++) c = c * (unsigned)(n - t) / (unsigned)(t + 1);
                if (n < k) c = 0;
                if ((unsigned)r < c) { m[i] = v - i; prev = v + 1; break; }
                r -= (int)c;
                v++;
            }
        }
        unsigned u = 0;
        int fact = 1, run = 1;
#pragma unroll
        for (int i = 0; i < 5; i++) {
            u |= ((unsigned)m[i]) << (4 * i);
            if (i && m[i] == m[i - 1]) { run++; fact *= run; }
            else run = 1;
        }
        g_states[s]  = u;
        g_invfact[s] = 1.0f / ((float)fact * 256.0f);   // Glynn 2^{2(1-n)} folded in
        return;
    }

    // ---- MLP for 2 batch rows per block ----
    int b0 = (blk - 16) * 2;
    __shared__ __align__(16) float xs[2 * IN_DIM];
    __shared__ float  hs[2][HIDDEN];
    __shared__ float2 ph[2][MODES];

    for (int i = tid; i < 2 * IN_DIM; i += 128) xs[i] = x[b0 * IN_DIM + i];
    __syncthreads();

    if (tid < HIDDEN) {
        const float4* w4 = (const float4*)(W1 + tid * IN_DIM);
        const float4* x0 = (const float4*)xs;
        const float4* x1 = (const float4*)(xs + IN_DIM);
        float a0 = 0.f, a1 = 0.f, c0 = 0.f, c1 = 0.f;
#pragma unroll 4
        for (int i = 0; i < IN_DIM / 4; i++) {
            float4 wv = w4[i], v0 = x0[i], v1 = x1[i];
            a0 = fmaf(wv.x, v0.x, a0); a0 = fmaf(wv.y, v0.y, a0);
            c0 = fmaf(wv.z, v0.z, c0); c0 = fmaf(wv.w, v0.w, c0);
            a1 = fmaf(wv.x, v1.x, a1); a1 = fmaf(wv.y, v1.y, a1);
            c1 = fmaf(wv.z, v1.z, c1); c1 = fmaf(wv.w, v1.w, c1);
        }
        float bb = b1[tid];
        float z0 = a0 + c0 + bb, z1 = a1 + c1 + bb;
        hs[0][tid] = 1.0f / (1.0f + expf(-z0));
        hs[1][tid] = 1.0f / (1.0f + expf(-z1));
    }
    __syncthreads();

    if (tid < 20) {
        int bb = tid / 10, q = tid % 10;
        float th = 0.f;
#pragma unroll
        for (int j = 0; j < 10; j++) th += hs[bb][j * 10 + q];
        float sn, cn;
        sincosf(th, &sn, &cn);
        ph[bb][q] = make_float2(cn, sn);
    }
    __syncthreads();

    if (tid < 100) {
        int bb = tid / 50, pj = tid % 50;
        int p = pj / 5, j = pj % 5, c = 2 * j;   // IN_COLS = {0,2,4,6,8}
        float2 acc = make_float2(0.f, 0.f);
#pragma unroll
        for (int q = 0; q < MODES; q++) {
            float2 wr = make_float2(wrre[p * 10 + q], wrim[p * 10 + q]);
            float2 wl = make_float2(wlre[q * 10 + c], wlim[q * 10 + c]);
            float2 t  = cmul(cmul(wr, ph[bb][q]), wl);
            acc.x += t.x; acc.y += t.y;
        }
        g_A[(b0 + bb) * 50 + pj] = acc;
    }
}

// ---------------- kernel 2: Glynn permanents + fused W2 partial contraction
__global__ void __launch_bounds__(256) k_perm(const float* __restrict__ W2) {
    int b = blockIdx.y, chunk = blockIdx.x, tid = threadIdx.x;
    int s = chunk * 256 + tid;
    __shared__ float2 Ash[50];
    __shared__ float  red[NCLS][8];
    if (tid < 50) Ash[tid] = g_A[b * 50 + tid];
    __syncthreads();

    int sc = (s < NSTATES) ? s : (NSTATES - 1);
    unsigned u = g_states[sc];
    float2 row[5][5];
#pragma unroll
    for (int n = 0; n < 5; n++) {
        int r = (u >> (4 * n)) & 15;
#pragma unroll
        for (int j = 0; j < 5; j++) row[n][j] = Ash[r * 5 + j];
    }

    // Glynn: perm = 2^{1-n} sum_{delta, d0=+1} (prod d) prod_j (sum_i d_i row[i][j])
    float2 cs[5];
#pragma unroll
    for (int j = 0; j < 5; j++) {
        cs[j].x = ((row[0][j].x + row[1][j].x) + (row[2][j].x + row[3][j].x)) + row[4][j].x;
        cs[j].y = ((row[0][j].y + row[1][j].y) + (row[2][j].y + row[3][j].y)) + row[4][j].y;
    }
    float2 pr = cs[0];
#pragma unroll
    for (int j = 1; j < 5; j++) pr = cmul(pr, cs[j]);
    float2 acc = pr;                       // k = 0 term, sign +1

#pragma unroll
    for (int k = 1; k < 16; k++) {
        int rb = (k & 1) ? 1 : (k & 2) ? 2 : (k & 4) ? 3 : 4;   // ctz(k)+1
        unsigned ng = (unsigned)k ^ ((unsigned)k >> 1);
        float sg = ((ng >> (rb - 1)) & 1u) ? -2.f : 2.f;        // new delta value
#pragma unroll
        for (int j = 0; j < 5; j++) {
            cs[j].x = fmaf(sg, row[rb][j].x, cs[j].x);
            cs[j].y = fmaf(sg, row[rb][j].y, cs[j].y);
        }
        pr = cs[0];
#pragma unroll
        for (int j = 1; j < 5; j++) pr = cmul(pr, cs[j]);
        float s2 = (k & 1) ? -1.f : 1.f;                        // parity(gray(k)) = k&1
        acc.x = fmaf(s2, pr.x, acc.x);
        acc.y = fmaf(s2, pr.y, acc.y);
    }

    float p = (acc.x * acc.x + acc.y * acc.y) * g_invfact[sc];
    if (s >= NSTATES) p = 0.f;

    // fused  prob @ W2^T  partial reduction
    int lane = tid & 31, w = tid >> 5;
#pragma unroll
    for (int c = 0; c < NCLS; c++) {
        float v = p * W2[c * NSTATES + sc];
#pragma unroll
        for (int o = 16; o; o >>= 1) v += __shfl_down_sync(0xffffffffu, v, o);
        if (lane == 0) red[c][w] = v;
    }
    __syncthreads();
    if (tid < NCLS) {
        float v = 0.f;
#pragma unroll
        for (int ww = 0; ww < 8; ww++) v += red[tid][ww];
        g_part[(b * SCHUNKS + chunk) * NCLS + tid] = v;
    }
}

// ---------------- kernel 3: tiny final reduce ------------------------------
__global__ void k_fin(const float* __restrict__ b2, float* __restrict__ out) {
    int idx = blockIdx.x * 256 + threadIdx.x;
    if (idx >= BATCH * NCLS) return;
    int b = idx / NCLS, c = idx % NCLS;
    float v = b2[c];
#pragma unroll
    for (int k = 0; k < SCHUNKS; k++) v += g_part[(b * SCHUNKS + k) * NCLS + c];
    out[idx] = v;
}

// ---------------- launch ---------------------------------------------------
extern "C" void kernel_launch(void* const* d_in, const int* in_sizes, int n_in,
                              void* d_out, int out_size) {
    const float* x    = (const float*)d_in[0];
    const float* W1   = (const float*)d_in[1];
    const float* b1   = (const float*)d_in[2];
    const float* wlre = (const float*)d_in[3];
    const float* wlim = (const float*)d_in[4];
    const float* wrre = (const float*)d_in[5];
    const float* wrim = (const float*)d_in[6];
    const float* W2   = (const float*)d_in[7];
    const float* b2   = (const float*)d_in[8];
    float* out = (float*)d_out;

    k_front<<<16 + BATCH / 2, 128>>>(x, W1, b1, wlre, wlim, wrre, wrim);
    dim3 gp(SCHUNKS, BATCH);
    k_perm<<<gp, 256>>>(W2);
    k_fin<<<(BATCH * NCLS + 255) / 256, 256>>>(b2, out);
}

// round 4
// speedup vs baseline: 1.7304x; 1.7207x over previous
#include <cuda_runtime.h>
#include <math.h>

#define BATCH   128
#define IN_DIM  784
#define HIDDEN  100
#define MODES   10
#define NSTATES 2002
#define NCLS    10
#define SCHUNKS 8

// ---------------- scratch (__device__ globals; no allocation allowed) ------
__device__ float g_h[BATCH * HIDDEN];               // sigmoid activations
__device__ float g_part[BATCH * SCHUNKS * NCLS];    // partial W2 sums

// binomial C(n,k), n=0..13, k=0..4 (plain global; L1-cached, divergence-ok)
__device__ const short g_binom[14][5] = {
    {1, 0, 0, 0, 0},  {1, 1, 0, 0, 0},   {1, 2, 1, 0, 0},    {1, 3, 3, 1, 0},
    {1, 4, 6, 4, 1},  {1, 5,10,10, 5},   {1, 6,15,20,15},    {1, 7,21,35,35},
    {1, 8,28,56,70},  {1, 9,36,84,126},  {1,10,45,120,210},  {1,11,55,165,330},
    {1,12,66,220,495},{1,13,78,286,715}
};

__device__ __forceinline__ float2 cmul(float2 a, float2 b) {
    return make_float2(fmaf(a.x, b.x, -(a.y * b.y)),
                       fmaf(a.x, b.y,  a.y * b.x));
}

// ---------------- kernel 1: MLP (4b x 4h register-blocked warp GEMM) ------
__global__ void __launch_bounds__(256) k_mlp(const float* __restrict__ x,
                                             const float* __restrict__ W1,
                                             const float* __restrict__ b1) {
    int w    = blockIdx.x * 8 + (threadIdx.x >> 5);       // 800 warps
    int lane = threadIdx.x & 31;
    if (w >= 32 * 25) return;
    int b0 = (w & 31) * 4;        // 32 batch tiles
    int h0 = (w >> 5) * 4;        // 25 hidden tiles

    const float4* xr0 = (const float4*)(x  + (b0 + 0) * IN_DIM);
    const float4* xr1 = (const float4*)(x  + (b0 + 1) * IN_DIM);
    const float4* xr2 = (const float4*)(x  + (b0 + 2) * IN_DIM);
    const float4* xr3 = (const float4*)(x  + (b0 + 3) * IN_DIM);
    const float4* wr0 = (const float4*)(W1 + (h0 + 0) * IN_DIM);
    const float4* wr1 = (const float4*)(W1 + (h0 + 1) * IN_DIM);
    const float4* wr2 = (const float4*)(W1 + (h0 + 2) * IN_DIM);
    const float4* wr3 = (const float4*)(W1 + (h0 + 3) * IN_DIM);

    float acc[4][4];
#pragma unroll
    for (int i = 0; i < 4; i++)
#pragma unroll
        for (int j = 0; j < 4; j++) acc[i][j] = 0.f;

    const float4 z4 = make_float4(0.f, 0.f, 0.f, 0.f);
#pragma unroll
    for (int t = 0; t < 7; t++) {                 // 196 float4 per row
        int idx = lane + 32 * t;
        bool ok = (idx < IN_DIM / 4);
        float4 xv[4], wv[4];
        xv[0] = ok ? xr0[idx] : z4;  xv[1] = ok ? xr1[idx] : z4;
        xv[2] = ok ? xr2[idx] : z4;  xv[3] = ok ? xr3[idx] : z4;
        wv[0] = ok ? wr0[idx] : z4;  wv[1] = ok ? wr1[idx] : z4;
        wv[2] = ok ? wr2[idx] : z4;  wv[3] = ok ? wr3[idx] : z4;
#pragma unroll
        for (int i = 0; i < 4; i++)
#pragma unroll
            for (int j = 0; j < 4; j++) {
                float d = fmaf(xv[i].x, wv[j].x,
                          fmaf(xv[i].y, wv[j].y,
                          fmaf(xv[i].z, wv[j].z, xv[i].w * wv[j].w)));
                acc[i][j] += d;
            }
    }

    // full butterfly: every lane ends with the total
#pragma unroll
    for (int i = 0; i < 4; i++)
#pragma unroll
        for (int j = 0; j < 4; j++) {
            float v = acc[i][j];
#pragma unroll
            for (int o = 16; o; o >>= 1) v += __shfl_xor_sync(0xffffffffu, v, o);
            acc[i][j] = v;
        }

    if (lane < 16) {
        int i = lane >> 2, j = lane & 3;
        float zv = acc[i][j] + b1[h0 + j];
        g_h[(b0 + i) * HIDDEN + h0 + j] = 1.0f / (1.0f + expf(-zv));
    }
}

// ---------------- kernel 2: phase+A, unrank, Glynn perm, fused W2 reduce --
__global__ void __launch_bounds__(256) k_perm(const float* __restrict__ wlre,
                                              const float* __restrict__ wlim,
                                              const float* __restrict__ wrre,
                                              const float* __restrict__ wrim,
                                              const float* __restrict__ W2) {
    int b = blockIdx.y, chunk = blockIdx.x, tid = threadIdx.x;
    __shared__ float2 ph[MODES];
    __shared__ float2 Ash[50];
    __shared__ float  red[NCLS][8];

    // phase: theta[q] = sum_j h[b, j*10+q]
    if (tid < MODES) {
        float th = 0.f;
#pragma unroll
        for (int j = 0; j < 10; j++) th += g_h[b * HIDDEN + j * 10 + tid];
        float sn, cn;
        sincosf(th, &sn, &cn);
        ph[tid] = make_float2(cn, sn);
    }
    __syncthreads();

    // A[p,j] = sum_q WR[p,q] * ph[q] * WL[q,2j]
    if (tid < 50) {
        int p = tid / 5, j = tid % 5, c = 2 * j;
        float2 acc = make_float2(0.f, 0.f);
#pragma unroll
        for (int q = 0; q < MODES; q++) {
            float2 wr = make_float2(wrre[p * 10 + q], wrim[p * 10 + q]);
            float2 wl = make_float2(wlre[q * 10 + c], wlim[q * 10 + c]);
            float2 t  = cmul(cmul(wr, ph[q]), wl);
            acc.x += t.x; acc.y += t.y;
        }
        Ash[tid] = acc;
    }
    __syncthreads();

    int s  = chunk * 256 + tid;
    int sc = (s < NSTATES) ? s : (NSTATES - 1);

    // inline unrank of combinations_with_replacement(10,5), rank sc
    int r = sc, prev = 0;
    int m[5];
    int fact = 1, run = 1;
#pragma unroll
    for (int i = 0; i < 5; i++) {
        int k = 4 - i;
        int v = prev;
        for (;;) {
            int c = g_binom[13 - v][k];
            if (r < c) break;
            r -= c;
            v++;
        }
        m[i] = v - i;
        prev = v + 1;
        if (i && m[i] == m[i - 1]) { run++; fact *= run; }
        else run = 1;
    }
    float invf = 1.0f / ((float)fact * 256.0f);   // Glynn 2^{2(1-n)} folded in

    float2 row[5][5];
#pragma unroll
    for (int n = 0; n < 5; n++) {
#pragma unroll
        for (int j = 0; j < 5; j++) row[n][j] = Ash[m[n] * 5 + j];
    }

    // Glynn: perm = 2^{1-n} sum_{delta, d0=+1} (prod d) prod_j (sum_i d_i row[i][j])
    float2 cs[5];
#pragma unroll
    for (int j = 0; j < 5; j++) {
        cs[j].x = ((row[0][j].x + row[1][j].x) + (row[2][j].x + row[3][j].x)) + row[4][j].x;
        cs[j].y = ((row[0][j].y + row[1][j].y) + (row[2][j].y + row[3][j].y)) + row[4][j].y;
    }
    float2 pr = cs[0];
#pragma unroll
    for (int j = 1; j < 5; j++) pr = cmul(pr, cs[j]);
    float2 acc = pr;                       // k = 0 term, sign +1

#pragma unroll
    for (int k = 1; k < 16; k++) {
        int rb = (k & 1) ? 1 : (k & 2) ? 2 : (k & 4) ? 3 : 4;   // ctz(k)+1
        unsigned ng = (unsigned)k ^ ((unsigned)k >> 1);
        float sg = ((ng >> (rb - 1)) & 1u) ? -2.f : 2.f;        // new delta value
#pragma unroll
        for (int j = 0; j < 5; j++) {
            cs[j].x = fmaf(sg, row[rb][j].x, cs[j].x);
            cs[j].y = fmaf(sg, row[rb][j].y, cs[j].y);
        }
        pr = cs[0];
#pragma unroll
        for (int j = 1; j < 5; j++) pr = cmul(pr, cs[j]);
        float s2 = (k & 1) ? -1.f : 1.f;                        // parity(gray(k))
        acc.x = fmaf(s2, pr.x, acc.x);
        acc.y = fmaf(s2, pr.y, acc.y);
    }

    float p = (acc.x * acc.x + acc.y * acc.y) * invf;
    if (s >= NSTATES) p = 0.f;

    // fused  prob @ W2^T  partial reduction
    int lane = tid & 31, w = tid >> 5;
#pragma unroll
    for (int c = 0; c < NCLS; c++) {
        float v = p * W2[c * NSTATES + sc];
#pragma unroll
        for (int o = 16; o; o >>= 1) v += __shfl_down_sync(0xffffffffu, v, o);
        if (lane == 0) red[c][w] = v;
    }
    __syncthreads();
    if (tid < NCLS) {
        float v = 0.f;
#pragma unroll
        for (int ww = 0; ww < 8; ww++) v += red[tid][ww];
        g_part[(b * SCHUNKS + chunk) * NCLS + tid] = v;
    }
}

// ---------------- kernel 3: tiny final reduce ------------------------------
__global__ void k_fin(const float* __restrict__ b2, float* __restrict__ out) {
    int idx = blockIdx.x * 256 + threadIdx.x;
    if (idx >= BATCH * NCLS) return;
    int b = idx / NCLS, c = idx % NCLS;
    float v = b2[c];
#pragma unroll
    for (int k = 0; k < SCHUNKS; k++) v += g_part[(b * SCHUNKS + k) * NCLS + c];
    out[idx] = v;
}

// ---------------- launch ---------------------------------------------------
extern "C" void kernel_launch(void* const* d_in, const int* in_sizes, int n_in,
                              void* d_out, int out_size) {
    const float* x    = (const float*)d_in[0];
    const float* W1   = (const float*)d_in[1];
    const float* b1   = (const float*)d_in[2];
    const float* wlre = (const float*)d_in[3];
    const float* wlim = (const float*)d_in[4];
    const float* wrre = (const float*)d_in[5];
    const float* wrim = (const float*)d_in[6];
    const float* W2   = (const float*)d_in[7];
    const float* b2   = (const float*)d_in[8];
    float* out = (float*)d_out;

    k_mlp<<<100, 256>>>(x, W1, b1);
    dim3 gp(SCHUNKS, BATCH);
    k_perm<<<gp, 256>>>(wlre, wlim, wrre, wrim, W2);
    k_fin<<<(BATCH * NCLS + 255) / 256, 256>>>(b2, out);
}